// round 9
// baseline (speedup 1.0000x reference)
#include <cuda_runtime.h>
#include <cuda_bf16.h>
#include <cstdint>

#define L_SEQ 8192
#define E_DIM 256
#define HDIM 256
#define G4 1024
#define T_TAGS 34
#define START_TAG 32
#define NEG_VAL -10000.0f

__device__ float g_x[L_SEQ * E_DIM];
__device__ float g_igf[L_SEQ * G4];
__device__ float g_igb[L_SEQ * G4];
__device__ float g_hf[L_SEQ * HDIM];
__device__ float g_hb[L_SEQ * HDIM];
__device__ float g_feats[L_SEQ * T_TAGS];
__device__ float g_la[L_SEQ * T_TAGS];
__device__ float g_lb[L_SEQ * T_TAGS];

__device__ __forceinline__ float neg_inf() { return __int_as_float(0xff800000); }
__device__ __forceinline__ float sigmoidf_(float x) { return __fdividef(1.f, 1.f + __expf(-x)); }
__device__ __forceinline__ float tanhf_(float x) {
    float ax = fabsf(x);
    float e = __expf(-2.f * ax);
    float r = __fdividef(1.f - e, 1.f + e);
    return x < 0.f ? -r : r;
}
__device__ __forceinline__ float ex2_(float x) { float y; asm("ex2.approx.ftz.f32 %0,%1;" : "=f"(y) : "f"(x)); return y; }
__device__ __forceinline__ float lg2_(float x) { float y; asm("lg2.approx.ftz.f32 %0,%1;" : "=f"(y) : "f"(x)); return y; }

// ------------- embedding gather -------------
__global__ void gather_kernel(const int* __restrict__ words, const float* __restrict__ embed) {
    int t = blockIdx.x;
    g_x[t * E_DIM + threadIdx.x] = embed[(long)words[t] * E_DIM + threadIdx.x];
}

// dummy kernel: shifts launch index so ncu's fixed skip lands on lstm_kernel
__global__ void dummy_kernel() {}

// ------------- input projections -------------
__global__ void igates_kernel(const float* __restrict__ Wih_f, const float* __restrict__ b_f,
                              const float* __restrict__ Wih_b, const float* __restrict__ b_b) {
    const float* W = blockIdx.z ? Wih_b : Wih_f;
    const float* b = blockIdx.z ? b_b : b_f;
    float* out = blockIdx.z ? g_igb : g_igf;
    __shared__ float ws[128][65];
    __shared__ __align__(16) float xsT[64][20];
    int tid = threadIdx.x;
    int t0 = blockIdx.x * 16, r0 = blockIdx.y * 128;
    float acc[16];
#pragma unroll
    for (int i = 0; i < 16; i++) acc[i] = 0.f;
    for (int kc = 0; kc < 4; kc++) {
        int kb = kc * 64;
        for (int i = tid; i < 1024; i += 128)
            xsT[i & 63][i >> 6] = g_x[(t0 + (i >> 6)) * E_DIM + kb + (i & 63)];
        for (int i = tid; i < 8192; i += 128)
            ws[i >> 6][i & 63] = W[(r0 + (i >> 6)) * E_DIM + kb + (i & 63)];
        __syncthreads();
#pragma unroll 8
        for (int k = 0; k < 64; k++) {
            float wv = ws[tid][k];
            float4 x0 = *(const float4*)&xsT[k][0];
            float4 x1 = *(const float4*)&xsT[k][4];
            float4 x2 = *(const float4*)&xsT[k][8];
            float4 x3 = *(const float4*)&xsT[k][12];
            acc[0] = fmaf(wv, x0.x, acc[0]);   acc[1] = fmaf(wv, x0.y, acc[1]);
            acc[2] = fmaf(wv, x0.z, acc[2]);   acc[3] = fmaf(wv, x0.w, acc[3]);
            acc[4] = fmaf(wv, x1.x, acc[4]);   acc[5] = fmaf(wv, x1.y, acc[5]);
            acc[6] = fmaf(wv, x1.z, acc[6]);   acc[7] = fmaf(wv, x1.w, acc[7]);
            acc[8] = fmaf(wv, x2.x, acc[8]);   acc[9] = fmaf(wv, x2.y, acc[9]);
            acc[10] = fmaf(wv, x2.z, acc[10]); acc[11] = fmaf(wv, x2.w, acc[11]);
            acc[12] = fmaf(wv, x3.x, acc[12]); acc[13] = fmaf(wv, x3.y, acc[13]);
            acc[14] = fmaf(wv, x3.z, acc[14]); acc[15] = fmaf(wv, x3.w, acc[15]);
        }
        __syncthreads();
    }
    float bias = b[r0 + tid];
#pragma unroll
    for (int tt = 0; tt < 16; tt++)
        out[(t0 + tt) * G4 + r0 + tid] = acc[tt] + bias;
}

// ------------- cluster-parallel persistent BiLSTM -------------
// FFMA2 GEMV + parallel tail (R6-proven). Sync: point-to-point monotone flags
// (8 DSMEM st.release per step per CTA) instead of barrier.cluster — bounded
// skew <=1 step, double-buffered hsm stays safe (sender enters step-t tail only
// after all CTAs finished step t-1's reads).
__global__ void __cluster_dims__(8, 1, 1) __launch_bounds__(512, 1)
lstm_kernel(const float* __restrict__ Whh_f, const float* __restrict__ Whh_b) {
    __shared__ __align__(16) float hsm[2][HDIM];
    __shared__ float part[512];
    __shared__ __align__(16) unsigned flags[8];

    int tid = threadIdx.x;
    int dir = blockIdx.x >> 3;
    unsigned rank;
    asm("mov.u32 %0, %%cluster_ctarank;" : "=r"(rank));
    const float* Whh = dir ? Whh_b : Whh_f;
    const float* ig = dir ? g_igb : g_igf;
    float* hout = dir ? g_hb : g_hf;

    int row_local = tid & 127;          // gate row within CTA
    int kseg = tid >> 7;                // warp-uniform k segment (0..3)
    int kb = kseg * 64;
    int g = row_local >> 5, u = row_local & 31;
    int unit = (int)rank * 32 + u;
    int grow = g * 256 + unit;

    // recurrent weights pre-packed as f32x2 pairs
    unsigned long long w2[32];
    {
        const float2* wp2 = (const float2*)(Whh + grow * 256 + kb);
#pragma unroll
        for (int i = 0; i < 32; i++) {
            float2 f = wp2[i];
            asm("mov.b64 %0, {%1,%2};" : "=l"(w2[i]) : "f"(f.x), "f"(f.y));
        }
    }

    hsm[tid >> 8][tid & 255] = 0.f;
    if (tid < 8) flags[tid] = 0;

    unsigned lh = (unsigned)__cvta_generic_to_shared(&hsm[0][0]);
    unsigned lf = (unsigned)__cvta_generic_to_shared(&flags[0]);
    unsigned base_h[8], base_f[8];
#pragma unroll
    for (int r = 0; r < 8; r++) {
        asm("mapa.shared::cluster.u32 %0, %1, %2;" : "=r"(base_h[r]) : "r"(lh), "r"(r));
        asm("mapa.shared::cluster.u32 %0, %1, %2;" : "=r"(base_f[r]) : "r"(lf), "r"(r));
    }
    unsigned own_f = base_f[rank];      // cluster-addressed view of our own flags

    __syncthreads();
    asm volatile("barrier.cluster.arrive.aligned;" ::: "memory");
    asm volatile("barrier.cluster.wait.aligned;" ::: "memory");

    float c_state = 0.f;
    int pos0 = dir ? (L_SEQ - 1) : 0;
    float ig_cur = (tid < 128) ? ig[pos0 * G4 + grow] : 0.f;

    for (int t = 0; t < L_SEQ; t++) {
        // wait for all 8 senders to have delivered h_{t-1} (flags >= t)
        if (t > 0) {
            if (tid < 8) {
                unsigned v;
                do {
                    asm volatile("ld.acquire.cluster.shared::cluster.u32 %0, [%1];"
                                 : "=r"(v) : "r"(own_f + tid * 4) : "memory");
                } while ((int)v < t);
            }
            __syncthreads();
        }

        // prefetch next step's input gate
        int posn = dir ? (L_SEQ - 2 - t) : (t + 1);
        float ig_nxt = (tid < 128 && t + 1 < L_SEQ) ? ig[posn * G4 + grow] : 0.f;

        // GEMV: 64-wide k-slice, packed FFMA2 (2 MAC/instr)
        const ulonglong2* hp = (const ulonglong2*)(hsm[t & 1] + kb);
        unsigned long long a0 = 0, a1 = 0;
#pragma unroll
        for (int i = 0; i < 16; i++) {
            ulonglong2 hv = hp[i];
            asm("fma.rn.f32x2 %0, %1, %2, %0;" : "+l"(a0) : "l"(w2[2 * i + 0]), "l"(hv.x));
            asm("fma.rn.f32x2 %0, %1, %2, %0;" : "+l"(a1) : "l"(w2[2 * i + 1]), "l"(hv.y));
        }
        float x0, x1, y0, y1;
        asm("mov.b64 {%0,%1}, %2;" : "=f"(x0), "=f"(x1) : "l"(a0));
        asm("mov.b64 {%0,%1}, %2;" : "=f"(y0), "=f"(y1) : "l"(a1));
        float a = (x0 + x1) + (y0 + y1);
        if (kseg == 0) a += ig_cur;         // fold input gate into segment 0
        part[kseg * 128 + row_local] = a;
        __syncthreads();

        // gate tail: 128 threads, quad = one hidden unit, lane%4 = gate
        if (tid < 128) {
            int uu = tid >> 2, gg = tid & 3;
            int row = gg * 32 + uu;
            float z = part[row] + part[128 + row] + part[256 + row] + part[384 + row];
            float act = (gg == 2) ? tanhf_(z) : sigmoidf_(z);
            int lq = tid & 31;
            float ai = __shfl_sync(0xffffffffu, act, (lq & ~3) + 0);
            float af = __shfl_sync(0xffffffffu, act, (lq & ~3) + 1);
            float ag = __shfl_sync(0xffffffffu, act, (lq & ~3) + 2);
            float ao = __shfl_sync(0xffffffffu, act, (lq & ~3) + 3);
            if (gg == 0) {
                c_state = fmaf(af, c_state, ai * ag);
                float h = ao * tanhf_(c_state);
                int pos = dir ? (L_SEQ - 1 - t) : t;
                int myu = (int)rank * 32 + uu;
                if (t + 1 < L_SEQ) {
                    unsigned slotoff = (unsigned)(((t + 1) & 1) * (HDIM * 4) + myu * 4);
#pragma unroll
                    for (int rr = 0; rr < 8; rr++)
                        asm volatile("st.shared::cluster.f32 [%0], %1;"
                                     :: "r"(base_h[rr] + slotoff), "f"(h) : "memory");
                }
                hout[pos * HDIM + myu] = h;
            }
        }
        ig_cur = ig_nxt;
        __syncthreads();   // all tail h-stores issued before the release below

        if (tid == 0 && t + 1 < L_SEQ) {
            unsigned val = (unsigned)(t + 1);
#pragma unroll
            for (int rr = 0; rr < 8; rr++)
                asm volatile("st.release.cluster.shared::cluster.u32 [%0], %1;"
                             :: "r"(base_f[rr] + rank * 4u), "r"(val) : "memory");
        }
    }
    asm volatile("barrier.cluster.arrive.aligned;" ::: "memory");
    asm volatile("barrier.cluster.wait.aligned;" ::: "memory");
}

// ------------- feats = [hf|hb] @ W_out^T + b_out -------------
__global__ void feats_kernel(const float* __restrict__ W_out, const float* __restrict__ b_out) {
    __shared__ float ws[T_TAGS][257];
    int tid = threadIdx.x;
    int tk = tid / 34, j = tid % 34;
    int t = blockIdx.x * 8 + tk;
    bool act = tid < 272;
    float acc = act ? b_out[j] : 0.f;
    for (int half = 0; half < 2; half++) {
        for (int i = tid; i < T_TAGS * 256; i += 288)
            ws[i >> 8][i & 255] = W_out[(i >> 8) * 512 + half * 256 + (i & 255)];
        __syncthreads();
        if (act) {
            const float* h = half ? &g_hb[t * HDIM] : &g_hf[t * HDIM];
#pragma unroll 4
            for (int k = 0; k < 256; k++) acc = fmaf(h[k], ws[j][k], acc);
        }
        __syncthreads();
    }
    if (act) g_feats[t * T_TAGS + j] = acc;
}

// ------------- CRF scans: log2 domain, 4-way i-split, quad shuffles -------------
__global__ void crf_kernel(const float* __restrict__ trans) {
    __shared__ float buf2[2][40];
    const float L2E = 1.4426950408889634f;
    const float LN2 = 0.6931471805599453f;
    int tid = threadIdx.x;
    int j = tid >> 2, s = tid & 3;
    bool act = j < 34;
    int ns = (s < 2) ? 9 : 8;

    if (blockIdx.x == 0) {
        float tr2[9];
        if (act) {
#pragma unroll
            for (int m = 0; m < 9; m++) {
                int i = s + 4 * m;
                tr2[m] = (i < 34) ? trans[j * T_TAGS + i] * L2E : 0.f;
            }
        }
        if (tid < 40) buf2[0][tid] = (tid == START_TAG) ? 0.f : NEG_VAL * L2E;
        float fcur = (act && s == 0) ? g_feats[j] * L2E : 0.f;
        __syncthreads();

        for (int t = 0; t < L_SEQ; t++) {
            float fnxt = (act && s == 0 && t + 1 < L_SEQ) ? g_feats[(t + 1) * T_TAGS + j] * L2E : 0.f;
            int w = t & 1;
            float v[9];
            float m0 = neg_inf();
            if (act) {
#pragma unroll
                for (int m = 0; m < 9; m++) {
                    if (m < ns) {
                        v[m] = buf2[w][s + 4 * m] + tr2[m];
                        m0 = fmaxf(m0, v[m]);
                    }
                }
            }
            m0 = fmaxf(m0, __shfl_xor_sync(0xffffffffu, m0, 1));
            m0 = fmaxf(m0, __shfl_xor_sync(0xffffffffu, m0, 2));
            float ss = 0.f;
            if (act) {
#pragma unroll
                for (int m = 0; m < 9; m++)
                    if (m < ns) ss += ex2_(v[m] - m0);
            }
            ss += __shfl_xor_sync(0xffffffffu, ss, 1);
            ss += __shfl_xor_sync(0xffffffffu, ss, 2);
            if (act && s == 0) {
                float v2 = m0 + lg2_(ss) + fcur;
                buf2[w ^ 1][j] = v2;
                g_la[t * T_TAGS + j] = v2 * LN2;
            }
            fcur = fnxt;
            __syncthreads();
        }
    } else {
        float tr2[9];
        if (act) {
#pragma unroll
            for (int m = 0; m < 9; m++) {
                int i = s + 4 * m;
                tr2[m] = (i < 34) ? trans[i * T_TAGS + j] * L2E : 0.f;
            }
        }
        {
            float m0 = neg_inf();
            if (act) {
#pragma unroll
                for (int m = 0; m < 9; m++)
                    if (m < ns) m0 = fmaxf(m0, tr2[m]);
            }
            m0 = fmaxf(m0, __shfl_xor_sync(0xffffffffu, m0, 1));
            m0 = fmaxf(m0, __shfl_xor_sync(0xffffffffu, m0, 2));
            float ss = 0.f;
            if (act) {
#pragma unroll
                for (int m = 0; m < 9; m++)
                    if (m < ns) ss += ex2_(tr2[m] - m0);
            }
            ss += __shfl_xor_sync(0xffffffffu, ss, 1);
            ss += __shfl_xor_sync(0xffffffffu, ss, 2);
            if (act && s == 0) {
                float v2 = m0 + lg2_(ss);
                buf2[0][j] = v2;
                g_lb[(L_SEQ - 1) * T_TAGS + j] = v2 * LN2;
            }
        }
        float fn[9];
        if (act) {
#pragma unroll
            for (int m = 0; m < 9; m++) {
                int i = s + 4 * m;
                fn[m] = (i < 34) ? g_feats[(L_SEQ - 1) * T_TAGS + i] * L2E : 0.f;
            }
        }
        __syncthreads();

        int w = 0;
        for (int t = L_SEQ - 2; t >= 0; t--) {
            float fnew[9];
            if (act && t > 0) {
#pragma unroll
                for (int m = 0; m < 9; m++) {
                    int i = s + 4 * m;
                    fnew[m] = (i < 34) ? g_feats[t * T_TAGS + i] * L2E : 0.f;
                }
            }
            float v[9];
            float m0 = neg_inf();
            if (act) {
#pragma unroll
                for (int m = 0; m < 9; m++) {
                    if (m < ns) {
                        v[m] = buf2[w][s + 4 * m] + fn[m] + tr2[m];
                        m0 = fmaxf(m0, v[m]);
                    }
                }
            }
            m0 = fmaxf(m0, __shfl_xor_sync(0xffffffffu, m0, 1));
            m0 = fmaxf(m0, __shfl_xor_sync(0xffffffffu, m0, 2));
            float ss = 0.f;
            if (act) {
#pragma unroll
                for (int m = 0; m < 9; m++)
                    if (m < ns) ss += ex2_(v[m] - m0);
            }
            ss += __shfl_xor_sync(0xffffffffu, ss, 1);
            ss += __shfl_xor_sync(0xffffffffu, ss, 2);
            if (act && s == 0) {
                float v2 = m0 + lg2_(ss);
                buf2[w ^ 1][j] = v2;
                g_lb[t * T_TAGS + j] = v2 * LN2;
            }
            if (act) {
#pragma unroll
                for (int m = 0; m < 9; m++) fn[m] = fnew[m];
            }
            w ^= 1;
            __syncthreads();
        }
    }
}

// ------------- score = la + lb, tags = argmax -------------
__global__ void finalize_kernel(float* out, int out_size) {
    int t = blockIdx.x * blockDim.x + threadIdx.x;
    if (t >= L_SEQ) return;
    bool has_score = out_size >= L_SEQ * T_TAGS;
    float best = neg_inf();
    int bj = 0;
#pragma unroll 2
    for (int jj = 0; jj < T_TAGS; jj++) {
        float v = g_la[t * T_TAGS + jj] + g_lb[t * T_TAGS + jj];
        if (has_score) out[t * T_TAGS + jj] = v;
        if (v > best) { best = v; bj = jj; }
    }
    if (out_size >= L_SEQ * T_TAGS + L_SEQ) out[L_SEQ * T_TAGS + t] = (float)bj;
    else if (out_size == L_SEQ) ((int*)out)[t] = bj;
}

extern "C" void kernel_launch(void* const* d_in, const int* in_sizes, int n_in,
                              void* d_out, int out_size) {
    const int* words   = (const int*)d_in[0];
    const float* embed = (const float*)d_in[1];
    const float* Wih_f = (const float*)d_in[2];
    const float* Whh_f = (const float*)d_in[3];
    const float* b_f   = (const float*)d_in[4];
    const float* Wih_b = (const float*)d_in[5];
    const float* Whh_b = (const float*)d_in[6];
    const float* b_b   = (const float*)d_in[7];
    const float* W_out = (const float*)d_in[8];
    const float* b_out = (const float*)d_in[9];
    const float* trans = (const float*)d_in[10];

    gather_kernel<<<L_SEQ, E_DIM>>>(words, embed);
    dim3 ig_grid(L_SEQ / 16, 8, 2);
    igates_kernel<<<ig_grid, 128>>>(Wih_f, b_f, Wih_b, b_b);
    dummy_kernel<<<1, 32>>>();              // shifts lstm to the profiled slot
    lstm_kernel<<<16, 512>>>(Whh_f, Whh_b);
    feats_kernel<<<L_SEQ / 8, 288>>>(W_out, b_out);
    crf_kernel<<<2, 160>>>(trans);
    finalize_kernel<<<(L_SEQ + 127) / 128, 128>>>((float*)d_out, out_size);
}

// round 10
// speedup vs baseline: 1.4832x; 1.4832x over previous
#include <cuda_runtime.h>
#include <cuda_bf16.h>
#include <cstdint>

#define L_SEQ 8192
#define E_DIM 256
#define HDIM 256
#define G4 1024
#define T_TAGS 34
#define START_TAG 32
#define NEG_VAL -10000.0f

__device__ float g_x[L_SEQ * E_DIM];
__device__ float g_igf[L_SEQ * G4];
__device__ float g_igb[L_SEQ * G4];
__device__ float g_hf[L_SEQ * HDIM];
__device__ float g_hb[L_SEQ * HDIM];
__device__ float g_feats[L_SEQ * T_TAGS];
__device__ float g_la[L_SEQ * T_TAGS];
__device__ float g_lb[L_SEQ * T_TAGS];

__device__ __forceinline__ float neg_inf() { return __int_as_float(0xff800000); }
__device__ __forceinline__ float sigmoidf_(float x) { return __fdividef(1.f, 1.f + __expf(-x)); }
__device__ __forceinline__ float tanhf_(float x) {
    float ax = fabsf(x);
    float e = __expf(-2.f * ax);
    float r = __fdividef(1.f - e, 1.f + e);
    return x < 0.f ? -r : r;
}
__device__ __forceinline__ float ex2_(float x) { float y; asm("ex2.approx.ftz.f32 %0,%1;" : "=f"(y) : "f"(x)); return y; }
__device__ __forceinline__ float lg2_(float x) { float y; asm("lg2.approx.ftz.f32 %0,%1;" : "=f"(y) : "f"(x)); return y; }

// ------------- embedding gather -------------
__global__ void gather_kernel(const int* __restrict__ words, const float* __restrict__ embed) {
    int t = blockIdx.x;
    g_x[t * E_DIM + threadIdx.x] = embed[(long)words[t] * E_DIM + threadIdx.x];
}

// dummy kernel: shifts launch index so ncu's fixed skip lands on lstm_kernel
__global__ void dummy_kernel() {}

// ------------- input projections -------------
__global__ void igates_kernel(const float* __restrict__ Wih_f, const float* __restrict__ b_f,
                              const float* __restrict__ Wih_b, const float* __restrict__ b_b) {
    const float* W = blockIdx.z ? Wih_b : Wih_f;
    const float* b = blockIdx.z ? b_b : b_f;
    float* out = blockIdx.z ? g_igb : g_igf;
    __shared__ float ws[128][65];
    __shared__ __align__(16) float xsT[64][20];
    int tid = threadIdx.x;
    int t0 = blockIdx.x * 16, r0 = blockIdx.y * 128;
    float acc[16];
#pragma unroll
    for (int i = 0; i < 16; i++) acc[i] = 0.f;
    for (int kc = 0; kc < 4; kc++) {
        int kb = kc * 64;
        for (int i = tid; i < 1024; i += 128)
            xsT[i & 63][i >> 6] = g_x[(t0 + (i >> 6)) * E_DIM + kb + (i & 63)];
        for (int i = tid; i < 8192; i += 128)
            ws[i >> 6][i & 63] = W[(r0 + (i >> 6)) * E_DIM + kb + (i & 63)];
        __syncthreads();
#pragma unroll 8
        for (int k = 0; k < 64; k++) {
            float wv = ws[tid][k];
            float4 x0 = *(const float4*)&xsT[k][0];
            float4 x1 = *(const float4*)&xsT[k][4];
            float4 x2 = *(const float4*)&xsT[k][8];
            float4 x3 = *(const float4*)&xsT[k][12];
            acc[0] = fmaf(wv, x0.x, acc[0]);   acc[1] = fmaf(wv, x0.y, acc[1]);
            acc[2] = fmaf(wv, x0.z, acc[2]);   acc[3] = fmaf(wv, x0.w, acc[3]);
            acc[4] = fmaf(wv, x1.x, acc[4]);   acc[5] = fmaf(wv, x1.y, acc[5]);
            acc[6] = fmaf(wv, x1.z, acc[6]);   acc[7] = fmaf(wv, x1.w, acc[7]);
            acc[8] = fmaf(wv, x2.x, acc[8]);   acc[9] = fmaf(wv, x2.y, acc[9]);
            acc[10] = fmaf(wv, x2.z, acc[10]); acc[11] = fmaf(wv, x2.w, acc[11]);
            acc[12] = fmaf(wv, x3.x, acc[12]); acc[13] = fmaf(wv, x3.y, acc[13]);
            acc[14] = fmaf(wv, x3.z, acc[14]); acc[15] = fmaf(wv, x3.w, acc[15]);
        }
        __syncthreads();
    }
    float bias = b[r0 + tid];
#pragma unroll
    for (int tt = 0; tt < 16; tt++)
        out[(t0 + tt) * G4 + r0 + tid] = acc[tt] + bias;
}

// ------------- cluster-parallel persistent BiLSTM -------------
// R6-proven body (FFMA2 GEMV + parallel tail). Sync: bounded-skew monotone
// flags with CHEAP primitives: weak remote flag stores behind ONE cluster
// fence; readers poll their own flags with local volatile LDS, then ONE fence.
__global__ void __cluster_dims__(8, 1, 1) __launch_bounds__(512, 1)
lstm_kernel(const float* __restrict__ Whh_f, const float* __restrict__ Whh_b) {
    __shared__ __align__(16) float hsm[2][HDIM];
    __shared__ float part[512];
    __shared__ __align__(16) unsigned flags[8];

    int tid = threadIdx.x;
    int dir = blockIdx.x >> 3;
    unsigned rank;
    asm("mov.u32 %0, %%cluster_ctarank;" : "=r"(rank));
    const float* Whh = dir ? Whh_b : Whh_f;
    const float* ig = dir ? g_igb : g_igf;
    float* hout = dir ? g_hb : g_hf;

    int row_local = tid & 127;          // gate row within CTA
    int kseg = tid >> 7;                // warp-uniform k segment (0..3)
    int kb = kseg * 64;
    int g = row_local >> 5, u = row_local & 31;
    int unit = (int)rank * 32 + u;
    int grow = g * 256 + unit;

    // recurrent weights pre-packed as f32x2 pairs
    unsigned long long w2[32];
    {
        const float2* wp2 = (const float2*)(Whh + grow * 256 + kb);
#pragma unroll
        for (int i = 0; i < 32; i++) {
            float2 f = wp2[i];
            asm("mov.b64 %0, {%1,%2};" : "=l"(w2[i]) : "f"(f.x), "f"(f.y));
        }
    }

    hsm[tid >> 8][tid & 255] = 0.f;
    if (tid < 8) flags[tid] = 0;

    unsigned lh = (unsigned)__cvta_generic_to_shared(&hsm[0][0]);
    unsigned lf = (unsigned)__cvta_generic_to_shared(&flags[0]);
    unsigned base_h[8], base_f[8];
#pragma unroll
    for (int r = 0; r < 8; r++) {
        asm("mapa.shared::cluster.u32 %0, %1, %2;" : "=r"(base_h[r]) : "r"(lh), "r"(r));
        asm("mapa.shared::cluster.u32 %0, %1, %2;" : "=r"(base_f[r]) : "r"(lf), "r"(r));
    }

    __syncthreads();
    asm volatile("barrier.cluster.arrive.aligned;" ::: "memory");
    asm volatile("barrier.cluster.wait.aligned;" ::: "memory");

    float c_state = 0.f;
    int pos0 = dir ? (L_SEQ - 1) : 0;
    float ig_cur = (tid < 128) ? ig[pos0 * G4 + grow] : 0.f;

    for (int t = 0; t < L_SEQ; t++) {
        // wait: all 8 senders delivered h for this step (flags >= t).
        // Poll is LOCAL (volatile LDS on own smem) — no cluster traffic.
        if (t > 0) {
            if (tid < 8) {
                unsigned v;
                do {
                    asm volatile("ld.volatile.shared.u32 %0, [%1];"
                                 : "=r"(v) : "r"(lf + tid * 4u));
                } while ((int)v < t);
                asm volatile("fence.acq_rel.cluster;" ::: "memory");
            }
            __syncthreads();
        }

        // prefetch next step's input gate
        int posn = dir ? (L_SEQ - 2 - t) : (t + 1);
        float ig_nxt = (tid < 128 && t + 1 < L_SEQ) ? ig[posn * G4 + grow] : 0.f;

        // GEMV: 64-wide k-slice, packed FFMA2 (2 MAC/instr)
        const ulonglong2* hp = (const ulonglong2*)(hsm[t & 1] + kb);
        unsigned long long a0 = 0, a1 = 0;
#pragma unroll
        for (int i = 0; i < 16; i++) {
            ulonglong2 hv = hp[i];
            asm("fma.rn.f32x2 %0, %1, %2, %0;" : "+l"(a0) : "l"(w2[2 * i + 0]), "l"(hv.x));
            asm("fma.rn.f32x2 %0, %1, %2, %0;" : "+l"(a1) : "l"(w2[2 * i + 1]), "l"(hv.y));
        }
        float x0, x1, y0, y1;
        asm("mov.b64 {%0,%1}, %2;" : "=f"(x0), "=f"(x1) : "l"(a0));
        asm("mov.b64 {%0,%1}, %2;" : "=f"(y0), "=f"(y1) : "l"(a1));
        float a = (x0 + x1) + (y0 + y1);
        if (kseg == 0) a += ig_cur;         // fold input gate into segment 0
        part[kseg * 128 + row_local] = a;
        __syncthreads();

        // gate tail: 128 threads, quad = one hidden unit, lane%4 = gate
        if (tid < 128) {
            int uu = tid >> 2, gg = tid & 3;
            int row = gg * 32 + uu;
            float z = part[row] + part[128 + row] + part[256 + row] + part[384 + row];
            float act = (gg == 2) ? tanhf_(z) : sigmoidf_(z);
            int lq = tid & 31;
            float ai = __shfl_sync(0xffffffffu, act, (lq & ~3) + 0);
            float af = __shfl_sync(0xffffffffu, act, (lq & ~3) + 1);
            float ag = __shfl_sync(0xffffffffu, act, (lq & ~3) + 2);
            float ao = __shfl_sync(0xffffffffu, act, (lq & ~3) + 3);
            if (gg == 0) {
                c_state = fmaf(af, c_state, ai * ag);
                float h = ao * tanhf_(c_state);
                int pos = dir ? (L_SEQ - 1 - t) : t;
                int myu = (int)rank * 32 + uu;
                if (t + 1 < L_SEQ) {
                    unsigned slotoff = (unsigned)(((t + 1) & 1) * (HDIM * 4) + myu * 4);
#pragma unroll
                    for (int rr = 0; rr < 8; rr++)
                        asm volatile("st.shared::cluster.f32 [%0], %1;"
                                     :: "r"(base_h[rr] + slotoff), "f"(h) : "memory");
                }
                hout[pos * HDIM + myu] = h;
            }
        }
        ig_cur = ig_nxt;
        __syncthreads();   // all tail h-stores ordered before the publish below

        // publish: ONE cluster fence, then 8 weak remote flag stores
        if (tid == 0 && t + 1 < L_SEQ) {
            asm volatile("fence.acq_rel.cluster;" ::: "memory");
            unsigned val = (unsigned)(t + 1);
#pragma unroll
            for (int rr = 0; rr < 8; rr++)
                asm volatile("st.shared::cluster.u32 [%0], %1;"
                             :: "r"(base_f[rr] + rank * 4u), "r"(val) : "memory");
        }
    }
    asm volatile("barrier.cluster.arrive.aligned;" ::: "memory");
    asm volatile("barrier.cluster.wait.aligned;" ::: "memory");
}

// ------------- feats = [hf|hb] @ W_out^T + b_out -------------
__global__ void feats_kernel(const float* __restrict__ W_out, const float* __restrict__ b_out) {
    __shared__ float ws[T_TAGS][257];
    int tid = threadIdx.x;
    int tk = tid / 34, j = tid % 34;
    int t = blockIdx.x * 8 + tk;
    bool act = tid < 272;
    float acc = act ? b_out[j] : 0.f;
    for (int half = 0; half < 2; half++) {
        for (int i = tid; i < T_TAGS * 256; i += 288)
            ws[i >> 8][i & 255] = W_out[(i >> 8) * 512 + half * 256 + (i & 255)];
        __syncthreads();
        if (act) {
            const float* h = half ? &g_hb[t * HDIM] : &g_hf[t * HDIM];
#pragma unroll 4
            for (int k = 0; k < 256; k++) acc = fmaf(h[k], ws[j][k], acc);
        }
        __syncthreads();
    }
    if (act) g_feats[t * T_TAGS + j] = acc;
}

// ------------- CRF scans: log2 domain, 4-way i-split, quad shuffles -------------
__global__ void crf_kernel(const float* __restrict__ trans) {
    __shared__ float buf2[2][40];
    const float L2E = 1.4426950408889634f;
    const float LN2 = 0.6931471805599453f;
    int tid = threadIdx.x;
    int j = tid >> 2, s = tid & 3;
    bool act = j < 34;
    int ns = (s < 2) ? 9 : 8;

    if (blockIdx.x == 0) {
        float tr2[9];
        if (act) {
#pragma unroll
            for (int m = 0; m < 9; m++) {
                int i = s + 4 * m;
                tr2[m] = (i < 34) ? trans[j * T_TAGS + i] * L2E : 0.f;
            }
        }
        if (tid < 40) buf2[0][tid] = (tid == START_TAG) ? 0.f : NEG_VAL * L2E;
        float fcur = (act && s == 0) ? g_feats[j] * L2E : 0.f;
        __syncthreads();

        for (int t = 0; t < L_SEQ; t++) {
            float fnxt = (act && s == 0 && t + 1 < L_SEQ) ? g_feats[(t + 1) * T_TAGS + j] * L2E : 0.f;
            int w = t & 1;
            float v[9];
            float m0 = neg_inf();
            if (act) {
#pragma unroll
                for (int m = 0; m < 9; m++) {
                    if (m < ns) {
                        v[m] = buf2[w][s + 4 * m] + tr2[m];
                        m0 = fmaxf(m0, v[m]);
                    }
                }
            }
            m0 = fmaxf(m0, __shfl_xor_sync(0xffffffffu, m0, 1));
            m0 = fmaxf(m0, __shfl_xor_sync(0xffffffffu, m0, 2));
            float ss = 0.f;
            if (act) {
#pragma unroll
                for (int m = 0; m < 9; m++)
                    if (m < ns) ss += ex2_(v[m] - m0);
            }
            ss += __shfl_xor_sync(0xffffffffu, ss, 1);
            ss += __shfl_xor_sync(0xffffffffu, ss, 2);
            if (act && s == 0) {
                float v2 = m0 + lg2_(ss) + fcur;
                buf2[w ^ 1][j] = v2;
                g_la[t * T_TAGS + j] = v2 * LN2;
            }
            fcur = fnxt;
            __syncthreads();
        }
    } else {
        float tr2[9];
        if (act) {
#pragma unroll
            for (int m = 0; m < 9; m++) {
                int i = s + 4 * m;
                tr2[m] = (i < 34) ? trans[i * T_TAGS + j] * L2E : 0.f;
            }
        }
        {
            float m0 = neg_inf();
            if (act) {
#pragma unroll
                for (int m = 0; m < 9; m++)
                    if (m < ns) m0 = fmaxf(m0, tr2[m]);
            }
            m0 = fmaxf(m0, __shfl_xor_sync(0xffffffffu, m0, 1));
            m0 = fmaxf(m0, __shfl_xor_sync(0xffffffffu, m0, 2));
            float ss = 0.f;
            if (act) {
#pragma unroll
                for (int m = 0; m < 9; m++)
                    if (m < ns) ss += ex2_(tr2[m] - m0);
            }
            ss += __shfl_xor_sync(0xffffffffu, ss, 1);
            ss += __shfl_xor_sync(0xffffffffu, ss, 2);
            if (act && s == 0) {
                float v2 = m0 + lg2_(ss);
                buf2[0][j] = v2;
                g_lb[(L_SEQ - 1) * T_TAGS + j] = v2 * LN2;
            }
        }
        float fn[9];
        if (act) {
#pragma unroll
            for (int m = 0; m < 9; m++) {
                int i = s + 4 * m;
                fn[m] = (i < 34) ? g_feats[(L_SEQ - 1) * T_TAGS + i] * L2E : 0.f;
            }
        }
        __syncthreads();

        int w = 0;
        for (int t = L_SEQ - 2; t >= 0; t--) {
            float fnew[9];
            if (act && t > 0) {
#pragma unroll
                for (int m = 0; m < 9; m++) {
                    int i = s + 4 * m;
                    fnew[m] = (i < 34) ? g_feats[t * T_TAGS + i] * L2E : 0.f;
                }
            }
            float v[9];
            float m0 = neg_inf();
            if (act) {
#pragma unroll
                for (int m = 0; m < 9; m++) {
                    if (m < ns) {
                        v[m] = buf2[w][s + 4 * m] + fn[m] + tr2[m];
                        m0 = fmaxf(m0, v[m]);
                    }
                }
            }
            m0 = fmaxf(m0, __shfl_xor_sync(0xffffffffu, m0, 1));
            m0 = fmaxf(m0, __shfl_xor_sync(0xffffffffu, m0, 2));
            float ss = 0.f;
            if (act) {
#pragma unroll
                for (int m = 0; m < 9; m++)
                    if (m < ns) ss += ex2_(v[m] - m0);
            }
            ss += __shfl_xor_sync(0xffffffffu, ss, 1);
            ss += __shfl_xor_sync(0xffffffffu, ss, 2);
            if (act && s == 0) {
                float v2 = m0 + lg2_(ss);
                buf2[w ^ 1][j] = v2;
                g_lb[t * T_TAGS + j] = v2 * LN2;
            }
            if (act) {
#pragma unroll
                for (int m = 0; m < 9; m++) fn[m] = fnew[m];
            }
            w ^= 1;
            __syncthreads();
        }
    }
}

// ------------- score = la + lb, tags = argmax -------------
__global__ void finalize_kernel(float* out, int out_size) {
    int t = blockIdx.x * blockDim.x + threadIdx.x;
    if (t >= L_SEQ) return;
    bool has_score = out_size >= L_SEQ * T_TAGS;
    float best = neg_inf();
    int bj = 0;
#pragma unroll 2
    for (int jj = 0; jj < T_TAGS; jj++) {
        float v = g_la[t * T_TAGS + jj] + g_lb[t * T_TAGS + jj];
        if (has_score) out[t * T_TAGS + jj] = v;
        if (v > best) { best = v; bj = jj; }
    }
    if (out_size >= L_SEQ * T_TAGS + L_SEQ) out[L_SEQ * T_TAGS + t] = (float)bj;
    else if (out_size == L_SEQ) ((int*)out)[t] = bj;
}

extern "C" void kernel_launch(void* const* d_in, const int* in_sizes, int n_in,
                              void* d_out, int out_size) {
    const int* words   = (const int*)d_in[0];
    const float* embed = (const float*)d_in[1];
    const float* Wih_f = (const float*)d_in[2];
    const float* Whh_f = (const float*)d_in[3];
    const float* b_f   = (const float*)d_in[4];
    const float* Wih_b = (const float*)d_in[5];
    const float* Whh_b = (const float*)d_in[6];
    const float* b_b   = (const float*)d_in[7];
    const float* W_out = (const float*)d_in[8];
    const float* b_out = (const float*)d_in[9];
    const float* trans = (const float*)d_in[10];

    gather_kernel<<<L_SEQ, E_DIM>>>(words, embed);
    dim3 ig_grid(L_SEQ / 16, 8, 2);
    igates_kernel<<<ig_grid, 128>>>(Wih_f, b_f, Wih_b, b_b);
    dummy_kernel<<<1, 32>>>();              // keeps lstm in the profiled slot
    lstm_kernel<<<16, 512>>>(Whh_f, Whh_b);
    feats_kernel<<<L_SEQ / 8, 288>>>(W_out, b_out);
    crf_kernel<<<2, 160>>>(trans);
    finalize_kernel<<<(L_SEQ + 127) / 128, 128>>>((float*)d_out, out_size);
}

// round 11
// speedup vs baseline: 2.1557x; 1.4535x over previous
#include <cuda_runtime.h>
#include <cuda_bf16.h>
#include <cstdint>

#define L_SEQ 8192
#define E_DIM 256
#define HDIM 256
#define G4 1024
#define T_TAGS 34
#define START_TAG 32
#define NEG_VAL -10000.0f

__device__ float g_x[L_SEQ * E_DIM];
__device__ float g_igf[L_SEQ * G4];
__device__ float g_igb[L_SEQ * G4];
__device__ float g_hf[L_SEQ * HDIM];
__device__ float g_hb[L_SEQ * HDIM];
__device__ float g_feats[L_SEQ * T_TAGS];
__device__ float g_la[L_SEQ * T_TAGS];
__device__ float g_lb[L_SEQ * T_TAGS];

__device__ __forceinline__ float neg_inf() { return __int_as_float(0xff800000); }
__device__ __forceinline__ float sigmoidf_(float x) { return __fdividef(1.f, 1.f + __expf(-x)); }
__device__ __forceinline__ float tanhf_(float x) {
    float ax = fabsf(x);
    float e = __expf(-2.f * ax);
    float r = __fdividef(1.f - e, 1.f + e);
    return x < 0.f ? -r : r;
}
__device__ __forceinline__ float ex2_(float x) { float y; asm("ex2.approx.ftz.f32 %0,%1;" : "=f"(y) : "f"(x)); return y; }
__device__ __forceinline__ float lg2_(float x) { float y; asm("lg2.approx.ftz.f32 %0,%1;" : "=f"(y) : "f"(x)); return y; }

// ------------- embedding gather -------------
__global__ void gather_kernel(const int* __restrict__ words, const float* __restrict__ embed) {
    int t = blockIdx.x;
    g_x[t * E_DIM + threadIdx.x] = embed[(long)words[t] * E_DIM + threadIdx.x];
}

// dummy kernel: keeps lstm_kernel in the ncu-profiled launch slot
__global__ void dummy_kernel() {}

// ------------- input projections (FFMA2 inner loop) -------------
__global__ void igates_kernel(const float* __restrict__ Wih_f, const float* __restrict__ b_f,
                              const float* __restrict__ Wih_b, const float* __restrict__ b_b) {
    const float* W = blockIdx.z ? Wih_b : Wih_f;
    const float* b = blockIdx.z ? b_b : b_f;
    float* out = blockIdx.z ? g_igb : g_igf;
    __shared__ float ws[128][65];
    __shared__ __align__(16) float xsT[64][20];
    int tid = threadIdx.x;
    int t0 = blockIdx.x * 16, r0 = blockIdx.y * 128;
    // acc2[p] holds packed sums for tokens (2p, 2p+1)
    unsigned long long acc2[8];
#pragma unroll
    for (int i = 0; i < 8; i++) acc2[i] = 0ull;
    for (int kc = 0; kc < 4; kc++) {
        int kb = kc * 64;
        for (int i = tid; i < 1024; i += 128)
            xsT[i & 63][i >> 6] = g_x[(t0 + (i >> 6)) * E_DIM + kb + (i & 63)];
        for (int i = tid; i < 8192; i += 128)
            ws[i >> 6][i & 63] = W[(r0 + (i >> 6)) * E_DIM + kb + (i & 63)];
        __syncthreads();
#pragma unroll 8
        for (int k = 0; k < 64; k++) {
            float wv = ws[tid][k];
            unsigned long long wv2;
            asm("mov.b64 %0, {%1,%1};" : "=l"(wv2) : "f"(wv));
            const ulonglong2* xp = (const ulonglong2*)&xsT[k][0];
#pragma unroll
            for (int q = 0; q < 4; q++) {
                ulonglong2 xv = xp[q];   // .x = tokens(4q,4q+1), .y = tokens(4q+2,4q+3)
                asm("fma.rn.f32x2 %0, %1, %2, %0;" : "+l"(acc2[2 * q + 0]) : "l"(wv2), "l"(xv.x));
                asm("fma.rn.f32x2 %0, %1, %2, %0;" : "+l"(acc2[2 * q + 1]) : "l"(wv2), "l"(xv.y));
            }
        }
        __syncthreads();
    }
    float bias = b[r0 + tid];
#pragma unroll
    for (int p = 0; p < 8; p++) {
        float lo, hi;
        asm("mov.b64 {%0,%1}, %2;" : "=f"(lo), "=f"(hi) : "l"(acc2[p]));
        out[(t0 + 2 * p + 0) * G4 + r0 + tid] = lo + bias;
        out[(t0 + 2 * p + 1) * G4 + r0 + tid] = hi + bias;
    }
}

// ------------- cluster-parallel persistent BiLSTM (R6-proven, unchanged) -------------
__global__ void __cluster_dims__(8, 1, 1) __launch_bounds__(512, 1)
lstm_kernel(const float* __restrict__ Whh_f, const float* __restrict__ Whh_b) {
    __shared__ __align__(16) float hsm[2][HDIM];
    __shared__ float part[512];

    int tid = threadIdx.x;
    int dir = blockIdx.x >> 3;
    unsigned rank;
    asm("mov.u32 %0, %%cluster_ctarank;" : "=r"(rank));
    const float* Whh = dir ? Whh_b : Whh_f;
    const float* ig = dir ? g_igb : g_igf;
    float* hout = dir ? g_hb : g_hf;

    int row_local = tid & 127;
    int kseg = tid >> 7;
    int kb = kseg * 64;
    int g = row_local >> 5, u = row_local & 31;
    int unit = (int)rank * 32 + u;
    int grow = g * 256 + unit;

    unsigned long long w2[32];
    {
        const float2* wp2 = (const float2*)(Whh + grow * 256 + kb);
#pragma unroll
        for (int i = 0; i < 32; i++) {
            float2 f = wp2[i];
            asm("mov.b64 %0, {%1,%2};" : "=l"(w2[i]) : "f"(f.x), "f"(f.y));
        }
    }

    hsm[tid >> 8][tid & 255] = 0.f;

    unsigned lh = (unsigned)__cvta_generic_to_shared(&hsm[0][0]);
    unsigned base_h[8];
#pragma unroll
    for (int r = 0; r < 8; r++)
        asm("mapa.shared::cluster.u32 %0, %1, %2;" : "=r"(base_h[r]) : "r"(lh), "r"(r));

    __syncthreads();
    asm volatile("barrier.cluster.arrive.aligned;" ::: "memory");
    asm volatile("barrier.cluster.wait.aligned;" ::: "memory");

    float c_state = 0.f;
    int pos0 = dir ? (L_SEQ - 1) : 0;
    float ig_cur = (tid < 128) ? ig[pos0 * G4 + grow] : 0.f;

    for (int t = 0; t < L_SEQ; t++) {
        int posn = dir ? (L_SEQ - 2 - t) : (t + 1);
        float ig_nxt = (tid < 128 && t + 1 < L_SEQ) ? ig[posn * G4 + grow] : 0.f;

        const ulonglong2* hp = (const ulonglong2*)(hsm[t & 1] + kb);
        unsigned long long a0 = 0, a1 = 0;
#pragma unroll
        for (int i = 0; i < 16; i++) {
            ulonglong2 hv = hp[i];
            asm("fma.rn.f32x2 %0, %1, %2, %0;" : "+l"(a0) : "l"(w2[2 * i + 0]), "l"(hv.x));
            asm("fma.rn.f32x2 %0, %1, %2, %0;" : "+l"(a1) : "l"(w2[2 * i + 1]), "l"(hv.y));
        }
        float x0, x1, y0, y1;
        asm("mov.b64 {%0,%1}, %2;" : "=f"(x0), "=f"(x1) : "l"(a0));
        asm("mov.b64 {%0,%1}, %2;" : "=f"(y0), "=f"(y1) : "l"(a1));
        float a = (x0 + x1) + (y0 + y1);
        if (kseg == 0) a += ig_cur;
        part[kseg * 128 + row_local] = a;
        __syncthreads();

        if (tid < 128) {
            int uu = tid >> 2, gg = tid & 3;
            int row = gg * 32 + uu;
            float z = part[row] + part[128 + row] + part[256 + row] + part[384 + row];
            float act = (gg == 2) ? tanhf_(z) : sigmoidf_(z);
            int lq = tid & 31;
            float ai = __shfl_sync(0xffffffffu, act, (lq & ~3) + 0);
            float af = __shfl_sync(0xffffffffu, act, (lq & ~3) + 1);
            float ag = __shfl_sync(0xffffffffu, act, (lq & ~3) + 2);
            float ao = __shfl_sync(0xffffffffu, act, (lq & ~3) + 3);
            if (gg == 0) {
                c_state = fmaf(af, c_state, ai * ag);
                float h = ao * tanhf_(c_state);
                int pos = dir ? (L_SEQ - 1 - t) : t;
                int myu = (int)rank * 32 + uu;
                hout[pos * HDIM + myu] = h;
                if (t + 1 < L_SEQ) {
                    unsigned slotoff = (unsigned)(((t + 1) & 1) * (HDIM * 4) + myu * 4);
#pragma unroll
                    for (int rr = 0; rr < 8; rr++)
                        asm volatile("st.shared::cluster.f32 [%0], %1;"
                                     :: "r"(base_h[rr] + slotoff), "f"(h) : "memory");
                }
            }
        }
        ig_cur = ig_nxt;
        asm volatile("barrier.cluster.arrive.aligned;" ::: "memory");
        asm volatile("barrier.cluster.wait.aligned;" ::: "memory");
    }
}

// ------------- feats = [hf|hb] @ W_out^T + b_out -------------
__global__ void feats_kernel(const float* __restrict__ W_out, const float* __restrict__ b_out) {
    __shared__ float ws[T_TAGS][257];
    int tid = threadIdx.x;
    int tk = tid / 34, j = tid % 34;
    int t = blockIdx.x * 8 + tk;
    bool act = tid < 272;
    float acc = act ? b_out[j] : 0.f;
    for (int half = 0; half < 2; half++) {
        for (int i = tid; i < T_TAGS * 256; i += 288)
            ws[i >> 8][i & 255] = W_out[(i >> 8) * 512 + half * 256 + (i & 255)];
        __syncthreads();
        if (act) {
            const float* h = half ? &g_hb[t * HDIM] : &g_hf[t * HDIM];
#pragma unroll 4
            for (int k = 0; k < 256; k++) acc = fmaf(h[k], ws[j][k], acc);
        }
        __syncthreads();
    }
    if (act) g_feats[t * T_TAGS + j] = acc;
}

// ------------- CRF scans: log2 domain + previous-output offset (no per-step max) -----
__global__ void crf_kernel(const float* __restrict__ trans) {
    __shared__ float buf2[2][40];
    const float L2E = 1.4426950408889634f;
    const float LN2 = 0.6931471805599453f;
    int tid = threadIdx.x;
    int j = tid >> 2, s = tid & 3;
    int lq = tid & 31;
    bool act = j < 34;
    int ns = (s < 2) ? 9 : 8;

    if (blockIdx.x == 0) {
        float tr2[9];
        if (act) {
#pragma unroll
            for (int m = 0; m < 9; m++) {
                int i = s + 4 * m;
                tr2[m] = (i < 34) ? trans[j * T_TAGS + i] * L2E : 0.f;
            }
        }
        if (tid < 40) buf2[0][tid] = (tid == START_TAG) ? 0.f : NEG_VAL * L2E;
        float fcur = (act && s == 0) ? g_feats[j] * L2E : 0.f;
        __syncthreads();

        float off;
        // ---- t = 0: exact max path (alpha_0 contains NEG entries) ----
        {
            float v[9];
            float m0 = neg_inf();
            if (act) {
#pragma unroll
                for (int m = 0; m < 9; m++)
                    if (m < ns) { v[m] = buf2[0][s + 4 * m] + tr2[m]; m0 = fmaxf(m0, v[m]); }
            }
            m0 = fmaxf(m0, __shfl_xor_sync(0xffffffffu, m0, 1));
            m0 = fmaxf(m0, __shfl_xor_sync(0xffffffffu, m0, 2));
            float ss = 0.f;
            if (act) {
#pragma unroll
                for (int m = 0; m < 9; m++)
                    if (m < ns) ss += ex2_(v[m] - m0);
            }
            ss += __shfl_xor_sync(0xffffffffu, ss, 1);
            ss += __shfl_xor_sync(0xffffffffu, ss, 2);
            float v2 = 0.f;
            if (act && s == 0) {
                v2 = m0 + lg2_(ss) + fcur;
                buf2[1][j] = v2;
                g_la[j] = v2 * LN2;
            }
            off = __shfl_sync(0xffffffffu, v2, lq & ~3);
            fcur = (act && s == 0) ? g_feats[T_TAGS + j] * L2E : 0.f;
            __syncthreads();
        }
        // ---- t >= 1: offset = previous alpha[j] (all finite, bounded spread) ----
        for (int t = 1; t < L_SEQ; t++) {
            float fnxt = (act && s == 0 && t + 1 < L_SEQ) ? g_feats[(t + 1) * T_TAGS + j] * L2E : 0.f;
            int w = t & 1;
            float ss = 0.f;
            if (act) {
#pragma unroll
                for (int m = 0; m < 9; m++)
                    if (m < ns) ss += ex2_(buf2[w][s + 4 * m] + tr2[m] - off);
            }
            ss += __shfl_xor_sync(0xffffffffu, ss, 1);
            ss += __shfl_xor_sync(0xffffffffu, ss, 2);
            float v2 = 0.f;
            if (act && s == 0) {
                v2 = off + lg2_(ss) + fcur;
                buf2[w ^ 1][j] = v2;
                g_la[t * T_TAGS + j] = v2 * LN2;
            }
            off = __shfl_sync(0xffffffffu, v2, lq & ~3);
            fcur = fnxt;
            __syncthreads();
        }
    } else {
        float tr2[9];
        if (act) {
#pragma unroll
            for (int m = 0; m < 9; m++) {
                int i = s + 4 * m;
                tr2[m] = (i < 34) ? trans[i * T_TAGS + j] * L2E : 0.f;
            }
        }
        float off;
        // ---- init: beta_last[j] = lse_i trans[i][j] (exact max) ----
        {
            float m0 = neg_inf();
            if (act) {
#pragma unroll
                for (int m = 0; m < 9; m++)
                    if (m < ns) m0 = fmaxf(m0, tr2[m]);
            }
            m0 = fmaxf(m0, __shfl_xor_sync(0xffffffffu, m0, 1));
            m0 = fmaxf(m0, __shfl_xor_sync(0xffffffffu, m0, 2));
            float ss = 0.f;
            if (act) {
#pragma unroll
                for (int m = 0; m < 9; m++)
                    if (m < ns) ss += ex2_(tr2[m] - m0);
            }
            ss += __shfl_xor_sync(0xffffffffu, ss, 1);
            ss += __shfl_xor_sync(0xffffffffu, ss, 2);
            float v2 = 0.f;
            if (act && s == 0) {
                v2 = m0 + lg2_(ss);
                buf2[0][j] = v2;
                g_lb[(L_SEQ - 1) * T_TAGS + j] = v2 * LN2;
            }
            off = __shfl_sync(0xffffffffu, v2, lq & ~3);
        }
        float fn[9];
        if (act) {
#pragma unroll
            for (int m = 0; m < 9; m++) {
                int i = s + 4 * m;
                fn[m] = (i < 34) ? g_feats[(L_SEQ - 1) * T_TAGS + i] * L2E : 0.f;
            }
        }
        __syncthreads();

        int w = 0;
        for (int t = L_SEQ - 2; t >= 0; t--) {
            float fnew[9];
            if (act && t > 0) {
#pragma unroll
                for (int m = 0; m < 9; m++) {
                    int i = s + 4 * m;
                    fnew[m] = (i < 34) ? g_feats[t * T_TAGS + i] * L2E : 0.f;
                }
            }
            float ss = 0.f;
            if (act) {
#pragma unroll
                for (int m = 0; m < 9; m++)
                    if (m < ns) ss += ex2_(buf2[w][s + 4 * m] + fn[m] + tr2[m] - off);
            }
            ss += __shfl_xor_sync(0xffffffffu, ss, 1);
            ss += __shfl_xor_sync(0xffffffffu, ss, 2);
            float v2 = 0.f;
            if (act && s == 0) {
                v2 = off + lg2_(ss);
                buf2[w ^ 1][j] = v2;
                g_lb[t * T_TAGS + j] = v2 * LN2;
            }
            off = __shfl_sync(0xffffffffu, v2, lq & ~3);
            if (act) {
#pragma unroll
                for (int m = 0; m < 9; m++) fn[m] = fnew[m];
            }
            w ^= 1;
            __syncthreads();
        }
    }
}

// ------------- score = la + lb, tags = argmax -------------
__global__ void finalize_kernel(float* out, int out_size) {
    int t = blockIdx.x * blockDim.x + threadIdx.x;
    if (t >= L_SEQ) return;
    bool has_score = out_size >= L_SEQ * T_TAGS;
    float best = neg_inf();
    int bj = 0;
#pragma unroll 2
    for (int jj = 0; jj < T_TAGS; jj++) {
        float v = g_la[t * T_TAGS + jj] + g_lb[t * T_TAGS + jj];
        if (has_score) out[t * T_TAGS + jj] = v;
        if (v > best) { best = v; bj = jj; }
    }
    if (out_size >= L_SEQ * T_TAGS + L_SEQ) out[L_SEQ * T_TAGS + t] = (float)bj;
    else if (out_size == L_SEQ) ((int*)out)[t] = bj;
}

extern "C" void kernel_launch(void* const* d_in, const int* in_sizes, int n_in,
                              void* d_out, int out_size) {
    const int* words   = (const int*)d_in[0];
    const float* embed = (const float*)d_in[1];
    const float* Wih_f = (const float*)d_in[2];
    const float* Whh_f = (const float*)d_in[3];
    const float* b_f   = (const float*)d_in[4];
    const float* Wih_b = (const float*)d_in[5];
    const float* Whh_b = (const float*)d_in[6];
    const float* b_b   = (const float*)d_in[7];
    const float* W_out = (const float*)d_in[8];
    const float* b_out = (const float*)d_in[9];
    const float* trans = (const float*)d_in[10];

    gather_kernel<<<L_SEQ, E_DIM>>>(words, embed);
    dim3 ig_grid(L_SEQ / 16, 8, 2);
    igates_kernel<<<ig_grid, 128>>>(Wih_f, b_f, Wih_b, b_b);
    dummy_kernel<<<1, 32>>>();              // keeps lstm in the profiled slot
    lstm_kernel<<<16, 512>>>(Whh_f, Whh_b);
    feats_kernel<<<L_SEQ / 8, 288>>>(W_out, b_out);
    crf_kernel<<<2, 160>>>(trans);
    finalize_kernel<<<(L_SEQ + 127) / 128, 128>>>((float*)d_out, out_size);
}